// round 7
// baseline (speedup 1.0000x reference)
#include <cuda_runtime.h>
#include <math.h>

#define Bc 4
#define Lc 32
#define Cc 32
#define Hc 128
#define Wc 128
#define HWc (Hc*Wc)
#define IMG_SLICE (Cc*HWc)

// Internal image buffers, channel-interleaved [B,L,H,W,C].
__device__ float g_imgA[(size_t)Bc*Lc*IMG_SLICE];   // transposed input (slice0 read-only) + ping-pong
__device__ float g_imgB[(size_t)Bc*Lc*IMG_SLICE];   // ping-pong
__device__ float g_imgF[(size_t)Bc*Lc*IMG_SLICE];   // finalized slices (HWC gather sources)
// Flow buffers, planar [B,L,2,H,W]
__device__ float g_flowA[(size_t)Bc*Lc*2*HWc];
__device__ float g_flowB[(size_t)Bc*Lc*2*HWc];
__device__ float g_flowF[(size_t)Bc*Lc*2*HWc];

// ---------------------------------------------------------------------------
// CHW -> HWC transpose of all input image slices.
__global__ void t_chw2hwc(const float* __restrict__ src, float* __restrict__ dst) {
    __shared__ float sm[32][65];
    int tile = blockIdx.x & 255;
    int sl   = blockIdx.x >> 8;
    int pix0 = tile * 64;
    const float* s = src + (size_t)sl * IMG_SLICE;
    float*       d = dst + (size_t)sl * IMG_SLICE;
    int tx = threadIdx.x & 63, ty = threadIdx.x >> 6;
    #pragma unroll
    for (int i = 0; i < 8; i++) {
        int c = ty + i * 4;
        sm[c][tx] = s[c * HWc + pix0 + tx];
    }
    __syncthreads();
    #pragma unroll
    for (int j = 0; j < 2; j++) {
        int u = threadIdx.x + j * 256;
        int p = u >> 3, q = u & 7;
        float4 v = make_float4(sm[4*q+0][p], sm[4*q+1][p], sm[4*q+2][p], sm[4*q+3][p]);
        *(float4*)(d + (size_t)(pix0 + p) * Cc + 4 * q) = v;
    }
}

// Output slice 0 = input images slice 0 (CHW copy).
__global__ void copy_slice0(const float* __restrict__ img, float* __restrict__ out) {
    int i = blockIdx.x * blockDim.x + threadIdx.x;
    const int per = IMG_SLICE / 4;
    const int n = Bc * per;
    if (i >= n) return;
    int b = i / per, r = i % per;
    const float4* s = (const float4*)(img + (size_t)b * Lc * IMG_SLICE) + r;
    float4*       d = (float4*)(out + (size_t)b * Lc * IMG_SLICE) + r;
    *d = *s;
}

// ---------------------------------------------------------------------------
// Grid/weight computation — VERBATIM the numerics that passed (R2/R5).
__device__ __forceinline__ void grid_weights(
    int pix, float qfx, float qfy,
    float& w00, float& w01, float& w10, float& w11,
    int& o00, int& o01, int& o10, int& o11)
{
    int h = pix >> 7;
    int w = pix & (Wc - 1);
    float gx = -1.0f + (2.0f / Wc) * ((float)w + 0.5f);
    float gy = -1.0f + (2.0f / Hc) * ((float)h + 0.5f);
    float fx = gx + qfx;
    float t  = fx + 1.0f;
    fx = t - 2.0f * floorf(t * 0.5f) - 1.0f;   // remainder(fx+1,2)-1 (x wrap)
    float fy = gy + qfy;

    float x = (fx + 1.0f) * (Wc * 0.5f) - 0.5f;
    float y = (fy + 1.0f) * (Hc * 0.5f) - 0.5f;
    float x0f = floorf(x), y0f = floorf(y);
    float tx = x - x0f, ty = y - y0f;
    int x0 = (int)x0f, y0 = (int)y0f;
    int x1 = x0 + 1,  y1 = y0 + 1;

    float vx0 = (x0 >= 0 && x0 < Wc) ? 1.0f : 0.0f;
    float vx1 = (x1 >= 0 && x1 < Wc) ? 1.0f : 0.0f;
    float vy0 = (y0 >= 0 && y0 < Hc) ? 1.0f : 0.0f;
    float vy1 = (y1 >= 0 && y1 < Hc) ? 1.0f : 0.0f;

    w00 = (1.0f - tx) * (1.0f - ty) * vx0 * vy0;
    w01 = tx * (1.0f - ty) * vx1 * vy0;
    w10 = (1.0f - tx) * ty * vx0 * vy1;
    w11 = tx * ty * vx1 * vy1;

    int cx0 = min(max(x0, 0), Wc - 1), cx1 = min(max(x1, 0), Wc - 1);
    int cy0 = min(max(y0, 0), Hc - 1), cy1 = min(max(y1, 0), Hc - 1);
    o00 = cy0 * Wc + cx0; o01 = cy0 * Wc + cx1;
    o10 = cy1 * Wc + cx0; o11 = cy1 * Wc + cx1;
}

// ---------------------------------------------------------------------------
// Flow compose (planar). grid = (HW/256, Lp, B).
__global__ void __launch_bounds__(256) compose_flow(int step,
    const float* __restrict__ srcFlow, const float* __restrict__ orgFlow,
    float* __restrict__ finFlow, float* __restrict__ dstFlow)
{
    int pix = blockIdx.x * 256 + threadIdx.x;
    int lp  = blockIdx.y;
    int b   = blockIdx.z;
    int l   = step + lp;

    const float* cf = srcFlow + (b * Lc + l) * (2 * HWc);
    float qfx = __ldg(cf + pix);
    float qfy = __ldg(cf + HWc + pix);

    float w00, w01, w10, w11; int o00, o01, o10, o11;
    grid_weights(pix, qfx, qfy, w00, w01, w10, w11, o00, o01, o10, o11);

    const float* pf = (lp == 0) ? (orgFlow + (b * Lc) * (2 * HWc))
                   : (lp < step) ? (finFlow + (b * Lc + lp) * (2 * HWc))
                                 : (srcFlow + (b * Lc + lp) * (2 * HWc));
    float* df = ((l < 2 * step) ? finFlow : dstFlow) + (b * Lc + l) * (2 * HWc);

    float s0 = w00 * __ldg(pf + o00) + w01 * __ldg(pf + o01)
             + w10 * __ldg(pf + o10) + w11 * __ldg(pf + o11);
    const float* pf1 = pf + HWc;
    float s1 = w00 * __ldg(pf1 + o00) + w01 * __ldg(pf1 + o01)
             + w10 * __ldg(pf1 + o10) + w11 * __ldg(pf1 + o11);
    df[pix]       = qfx + s0;
    df[HWc + pix] = qfy + s1;
}

// ---------------------------------------------------------------------------
// Image compose, 2 pixels per thread (second at +HW/2) for doubled MLP.
// Warp = 4 pixels x 8 channel-groups per pixel-set (1 L1 wavefront per tap).
// grid = (HW/64, Lp, B); block covers two 32-pixel strips.
// Finalized slices: stage both strips in smem, coalesced CHW stores to d_out.
__global__ void __launch_bounds__(256, 5) compose_img5(int step, int finHWC,
    const float* __restrict__ srcImg, const float* __restrict__ orgImg,
    float* __restrict__ finImg,       float* __restrict__ dstImg,
    const float* __restrict__ srcFlow, float* __restrict__ outImg)
{
    __shared__ float sm[2][32 * 33];
    int t   = threadIdx.x;
    int c4  = t & 7;
    int pl  = t >> 3;                  // pixel-local 0..31
    int lp  = blockIdx.y;
    int b   = blockIdx.z;
    int l   = step + lp;

    int pixA = blockIdx.x * 32 + pl;
    int pixB = pixA + HWc / 2;

    const float* cf = srcFlow + (b * Lc + l) * (2 * HWc);
    float qfxA = __ldg(cf + pixA);
    float qfyA = __ldg(cf + HWc + pixA);
    float qfxB = __ldg(cf + pixB);
    float qfyB = __ldg(cf + HWc + pixB);

    float wA00, wA01, wA10, wA11; int oA00, oA01, oA10, oA11;
    grid_weights(pixA, qfxA, qfyA, wA00, wA01, wA10, wA11, oA00, oA01, oA10, oA11);
    float wB00, wB01, wB10, wB11; int oB00, oB01, oB10, oB11;
    grid_weights(pixB, qfxB, qfyB, wB00, wB01, wB10, wB11, oB00, oB01, oB10, oB11);

    int co = c4 * 4;
    const float* pi = ((lp == 0) ? orgImg : (lp < step) ? finImg : srcImg)
                      + (b * Lc + lp) * IMG_SLICE;

    // issue all 10 independent loads up front
    float4 a00 = __ldg((const float4*)(pi + oA00 * Cc + co));
    float4 a01 = __ldg((const float4*)(pi + oA01 * Cc + co));
    float4 a10 = __ldg((const float4*)(pi + oA10 * Cc + co));
    float4 a11 = __ldg((const float4*)(pi + oA11 * Cc + co));
    float4 b00 = __ldg((const float4*)(pi + oB00 * Cc + co));
    float4 b01 = __ldg((const float4*)(pi + oB01 * Cc + co));
    float4 b10 = __ldg((const float4*)(pi + oB10 * Cc + co));
    float4 b11 = __ldg((const float4*)(pi + oB11 * Cc + co));

    int sliceOff = (b * Lc + l) * IMG_SLICE;
    int hwcA = sliceOff + pixA * Cc + co;
    int hwcB = sliceOff + pixB * Cc + co;
    float4 cvA = __ldcs((const float4*)(srcImg + hwcA));
    float4 cvB = __ldcs((const float4*)(srcImg + hwcB));

    float4 rA, rB;
    rA.x = cvA.x + wA00 * a00.x + wA01 * a01.x + wA10 * a10.x + wA11 * a11.x;
    rA.y = cvA.y + wA00 * a00.y + wA01 * a01.y + wA10 * a10.y + wA11 * a11.y;
    rA.z = cvA.z + wA00 * a00.z + wA01 * a01.z + wA10 * a10.z + wA11 * a11.z;
    rA.w = cvA.w + wA00 * a00.w + wA01 * a01.w + wA10 * a10.w + wA11 * a11.w;
    rB.x = cvB.x + wB00 * b00.x + wB01 * b01.x + wB10 * b10.x + wB11 * b11.x;
    rB.y = cvB.y + wB00 * b00.y + wB01 * b01.y + wB10 * b10.y + wB11 * b11.y;
    rB.z = cvB.z + wB00 * b00.z + wB01 * b01.z + wB10 * b10.z + wB11 * b11.z;
    rB.w = cvB.w + wB00 * b00.w + wB01 * b01.w + wB10 * b10.w + wB11 * b11.w;

    if (l < 2 * step) {                         // finalized (block-uniform)
        if (finHWC) {
            *(float4*)(finImg + hwcA) = rA;
            *(float4*)(finImg + hwcB) = rB;
        }
        int sb = pl * 33 + co;
        sm[0][sb + 0] = rA.x; sm[0][sb + 1] = rA.y;
        sm[0][sb + 2] = rA.z; sm[0][sb + 3] = rA.w;
        sm[1][sb + 0] = rB.x; sm[1][sb + 1] = rB.y;
        sm[1][sb + 2] = rB.z; sm[1][sb + 3] = rB.w;
        __syncthreads();
        int lane = t & 31, wp = t >> 5;
        float* oCA = outImg + sliceOff + blockIdx.x * 32 + lane;
        float* oCB = oCA + HWc / 2;
        #pragma unroll
        for (int i = 0; i < 4; i++) {
            int ch = wp * 4 + i;
            __stcs(oCA + ch * HWc, sm[0][lane * 33 + ch]);
            __stcs(oCB + ch * HWc, sm[1][lane * 33 + ch]);
        }
    } else {
        __stcs((float4*)(dstImg + hwcA), rA);
        __stcs((float4*)(dstImg + hwcB), rB);
    }
}

// ---------------------------------------------------------------------------
extern "C" void kernel_launch(void* const* d_in, const int* in_sizes, int n_in,
                              void* d_out, int out_size) {
    const float* flows  = (const float*)d_in[0];
    const float* images = (const float*)d_in[1];
    if (n_in >= 2 && in_sizes[0] > in_sizes[1]) {
        const float* tmp = flows; flows = images; images = tmp;
    }
    float* out = (float*)d_out;

    float *iA, *iB, *iF, *fA, *fB, *fF;
    cudaGetSymbolAddress((void**)&iA, g_imgA);
    cudaGetSymbolAddress((void**)&iB, g_imgB);
    cudaGetSymbolAddress((void**)&iF, g_imgF);
    cudaGetSymbolAddress((void**)&fA, g_flowA);
    cudaGetSymbolAddress((void**)&fB, g_flowB);
    cudaGetSymbolAddress((void**)&fF, g_flowF);

    // 1) transpose input images CHW -> HWC into iA
    t_chw2hwc<<<Bc * Lc * 256, 256>>>(images, iA);

    // 2) output slice 0 = input slice 0
    {
        int n = Bc * IMG_SLICE / 4;
        copy_slice0<<<(n + 255) / 256, 256>>>(images, out);
    }

    // 3) log-scan
    const float* sImg  = iA;    float* dImg  = iB;
    const float* sFlow = flows; float* dFlow = fB;
    for (int s = 1; s < Lc; s <<= 1) {
        int Lp = Lc - s;

        if (s < 16) {  // last step's flow output is never consumed
            dim3 gf(HWc / 256, Lp, Bc);
            compose_flow<<<gf, 256>>>(s, sFlow, flows, fF, dFlow);
        }
        int finHWC = (s < 16) ? 1 : 0;  // last step's finalized slices never re-gathered
        dim3 gi(HWc / 64, Lp, Bc);
        compose_img5<<<gi, 256>>>(s, finHWC, sImg, iA, iF, dImg, sFlow, out);

        const float* tI = sImg; sImg = dImg; dImg = (float*)tI;
        if (s == 1) { sFlow = fB; dFlow = fA; }
        else { const float* tF = sFlow; sFlow = dFlow; dFlow = (float*)tF; }
    }
}